// round 1
// baseline (speedup 1.0000x reference)
#include <cuda_runtime.h>

#define T_DIM 4
#define B_DIM 64
#define C_DIM 256
#define N_DIM 256
#define HEADS 8
#define DHEAD 32
#define TAU 0.5f
#define THRESH 1.0f
#define ATTN_THRESH 0.5f
#define BN_EPS 1e-5f

// ---------------- scratch (static device globals; no allocations) ----------------
// s spikes of input LIF: (T,B,C,N) fp32
__device__ float g_s[T_DIM * B_DIM * C_DIM * N_DIM];
// stacked q (rows 0..255) and k (rows 256..511) spikes: (T,B,512,N) fp32
__device__ float g_qk[T_DIM * B_DIM * 2 * C_DIM * N_DIM];
// attn spikes: (T,B,HEADS,N)
__device__ float g_attn[T_DIM * B_DIM * HEADS * N_DIM];

// ---------------- K1: LIF over raw input -> s ----------------
__global__ void k1_lif_input(const float* __restrict__ x) {
    const int stride = B_DIM * C_DIM * N_DIM;
    int i = blockIdx.x * blockDim.x + threadIdx.x;
    if (i >= stride) return;
    float mem = 0.f;
#pragma unroll
    for (int t = 0; t < T_DIM; t++) {
        mem = mem * TAU + x[t * stride + i];
        float sp = (mem >= THRESH) ? 1.f : 0.f;
        mem *= (1.f - sp);
        g_s[t * stride + i] = sp;
    }
}

// ---------------- K2: fused (q_w;k_w) GEMM + BN + LIF -> q,k spikes ----------------
// grid: (N/64, 512/64, B); block 256 threads; each thread: 4x4 microtile, t-loop inside
#define K2_CC 32
__global__ __launch_bounds__(256) void k2_qk(
    const float* __restrict__ wq, const float* __restrict__ wk,
    const float* __restrict__ qg, const float* __restrict__ qb,
    const float* __restrict__ qm, const float* __restrict__ qv,
    const float* __restrict__ kg, const float* __restrict__ kb,
    const float* __restrict__ km, const float* __restrict__ kv) {
    __shared__ float Ws[K2_CC][64];
    __shared__ float Ss[K2_CC][64];

    const int b  = blockIdx.z;
    const int ob = blockIdx.y * 64;   // 0..448 over stacked 512 rows
    const int nb = blockIdx.x * 64;
    const int tid = threadIdx.x;
    const int tx = tid & 15, ty = tid >> 4;

    // per-thread BN constants for its 4 output rows
    float inv[4], add[4];
#pragma unroll
    for (int i = 0; i < 4; i++) {
        int o = ob + ty * 4 + i;
        const float *g, *be, *me, *va;
        int oo;
        if (o < C_DIM) { g = qg; be = qb; me = qm; va = qv; oo = o; }
        else           { g = kg; be = kb; me = km; va = kv; oo = o - C_DIM; }
        float iv = g[oo] * rsqrtf(va[oo] + BN_EPS);
        inv[i] = iv;
        add[i] = be[oo] - me[oo] * iv;
    }

    float memr[4][4];
#pragma unroll
    for (int i = 0; i < 4; i++)
#pragma unroll
        for (int j = 0; j < 4; j++) memr[i][j] = 0.f;

    for (int t = 0; t < T_DIM; t++) {
        float acc[4][4] = {};
        const float* sbase = g_s + (size_t)(t * B_DIM + b) * C_DIM * N_DIM;

        for (int cc = 0; cc < C_DIM; cc += K2_CC) {
            // load weight tile Ws[c][o]
            for (int idx = tid; idx < 64 * K2_CC; idx += 256) {
                int ol = idx / K2_CC, cl = idx % K2_CC;
                int o = ob + ol;
                Ws[cl][ol] = (o < C_DIM) ? wq[o * C_DIM + cc + cl]
                                         : wk[(o - C_DIM) * C_DIM + cc + cl];
            }
            // load spike tile Ss[c][n]
            for (int idx = tid; idx < K2_CC * 64; idx += 256) {
                int cl = idx / 64, nl = idx % 64;
                Ss[cl][nl] = sbase[(cc + cl) * N_DIM + nb + nl];
            }
            __syncthreads();
#pragma unroll
            for (int cl = 0; cl < K2_CC; cl++) {
                const float4 wv = *reinterpret_cast<const float4*>(&Ws[cl][ty * 4]);
                const float4 sv = *reinterpret_cast<const float4*>(&Ss[cl][tx * 4]);
                float wr[4] = {wv.x, wv.y, wv.z, wv.w};
                float sr[4] = {sv.x, sv.y, sv.z, sv.w};
#pragma unroll
                for (int i = 0; i < 4; i++)
#pragma unroll
                    for (int j = 0; j < 4; j++)
                        acc[i][j] = fmaf(wr[i], sr[j], acc[i][j]);
            }
            __syncthreads();
        }

        // BN + LIF + store spikes
        float* qkbase = g_qk + (size_t)(t * B_DIM + b) * 2 * C_DIM * N_DIM;
#pragma unroll
        for (int i = 0; i < 4; i++) {
            float4 outv;
#pragma unroll
            for (int j = 0; j < 4; j++) {
                float v = acc[i][j] * inv[i] + add[i];
                float m = memr[i][j] * TAU + v;
                float sp = (m >= THRESH) ? 1.f : 0.f;
                memr[i][j] = m * (1.f - sp);
                reinterpret_cast<float*>(&outv)[j] = sp;
            }
            *reinterpret_cast<float4*>(
                &qkbase[(ob + ty * 4 + i) * N_DIM + nb + tx * 4]) = outv;
        }
    }
}

// ---------------- K3: per-head channel sums + decay memory + attn LIF ----------------
__global__ void k3_attn(const float* __restrict__ alpha_p) {
    int i = blockIdx.x * blockDim.x + threadIdx.x;  // over B*HEADS*N
    if (i >= B_DIM * HEADS * N_DIM) return;
    int n = i % N_DIM;
    int h = (i / N_DIM) % HEADS;
    int b = i / (N_DIM * HEADS);
    float a = *alpha_p;
    float M = 0.f, amem = 0.f;
#pragma unroll
    for (int t = 0; t < T_DIM; t++) {
        const float* qbase =
            g_qk + ((size_t)(t * B_DIM + b) * 2 * C_DIM + h * DHEAD) * N_DIM + n;
        float Q = 0.f;
#pragma unroll
        for (int d2 = 0; d2 < DHEAD; d2++) Q += qbase[d2 * N_DIM];
        M = (1.f - a) * M + a * Q;           // per-head summed decay memory
        float qs = M + Q;                     // sum_d (mems + q)
        amem = amem * TAU + qs;
        float sp = (amem >= ATTN_THRESH) ? 1.f : 0.f;
        amem *= (1.f - sp);
        g_attn[((t * B_DIM + b) * HEADS + h) * N_DIM + n] = sp;
    }
}

// ---------------- K4: proj GEMM over y = attn*k, + bias + BN -> out ----------------
// grid: (N/64, C/64, T*B)
__global__ __launch_bounds__(256) void k4_proj(
    const float* __restrict__ wp, const float* __restrict__ pbias,
    const float* __restrict__ pg, const float* __restrict__ pbeta,
    const float* __restrict__ pm, const float* __restrict__ pv,
    float* __restrict__ out) {
    __shared__ float Ws[K2_CC][64];
    __shared__ float Ss[K2_CC][64];

    const int tb = blockIdx.z;  // t*B + b
    const int ob = blockIdx.y * 64;
    const int nb = blockIdx.x * 64;
    const int tid = threadIdx.x;
    const int tx = tid & 15, ty = tid >> 4;

    float inv[4], add[4];
#pragma unroll
    for (int i = 0; i < 4; i++) {
        int o = ob + ty * 4 + i;
        float iv = pg[o] * rsqrtf(pv[o] + BN_EPS);
        inv[i] = iv;
        // (acc + bias)*iv + (beta - mean*iv)
        add[i] = pbias[o] * iv + pbeta[o] - pm[o] * iv;
    }

    float acc[4][4] = {};
    const float* kbase = g_qk + ((size_t)tb * 2 * C_DIM + C_DIM) * N_DIM;
    const float* abase = g_attn + (size_t)tb * HEADS * N_DIM;

    for (int cc = 0; cc < C_DIM; cc += K2_CC) {
        for (int idx = tid; idx < 64 * K2_CC; idx += 256) {
            int ol = idx / K2_CC, cl = idx % K2_CC;
            Ws[cl][ol] = wp[(ob + ol) * C_DIM + cc + cl];
        }
        for (int idx = tid; idx < K2_CC * 64; idx += 256) {
            int cl = idx / 64, nl = idx % 64;
            int c = cc + cl;
            float av = abase[(c >> 5) * N_DIM + nb + nl];  // head = c/32
            float kv2 = kbase[c * N_DIM + nb + nl];
            Ss[cl][nl] = av * kv2;                         // y = attn * k
        }
        __syncthreads();
#pragma unroll
        for (int cl = 0; cl < K2_CC; cl++) {
            const float4 wv = *reinterpret_cast<const float4*>(&Ws[cl][ty * 4]);
            const float4 sv = *reinterpret_cast<const float4*>(&Ss[cl][tx * 4]);
            float wr[4] = {wv.x, wv.y, wv.z, wv.w};
            float sr[4] = {sv.x, sv.y, sv.z, sv.w};
#pragma unroll
            for (int i = 0; i < 4; i++)
#pragma unroll
                for (int j = 0; j < 4; j++)
                    acc[i][j] = fmaf(wr[i], sr[j], acc[i][j]);
        }
        __syncthreads();
    }

#pragma unroll
    for (int i = 0; i < 4; i++) {
        float4 outv;
#pragma unroll
        for (int j = 0; j < 4; j++)
            reinterpret_cast<float*>(&outv)[j] = acc[i][j] * inv[i] + add[i];
        *reinterpret_cast<float4*>(
            &out[((size_t)tb * C_DIM + ob + ty * 4 + i) * N_DIM + nb + tx * 4]) = outv;
    }
}

// ---------------- launch ----------------
extern "C" void kernel_launch(void* const* d_in, const int* in_sizes, int n_in,
                              void* d_out, int out_size) {
    const float* x       = (const float*)d_in[0];
    const float* q_w     = (const float*)d_in[1];
    const float* q_gamma = (const float*)d_in[2];
    const float* q_beta  = (const float*)d_in[3];
    const float* q_mean  = (const float*)d_in[4];
    const float* q_var   = (const float*)d_in[5];
    const float* k_w     = (const float*)d_in[6];
    const float* k_gamma = (const float*)d_in[7];
    const float* k_beta  = (const float*)d_in[8];
    const float* k_mean  = (const float*)d_in[9];
    const float* k_var   = (const float*)d_in[10];
    const float* proj_w  = (const float*)d_in[11];
    const float* proj_b  = (const float*)d_in[12];
    const float* proj_g  = (const float*)d_in[13];
    const float* proj_be = (const float*)d_in[14];
    const float* proj_m  = (const float*)d_in[15];
    const float* proj_v  = (const float*)d_in[16];
    const float* alpha   = (const float*)d_in[17];
    float* out = (float*)d_out;

    // K1: input LIF
    {
        int total = B_DIM * C_DIM * N_DIM;
        k1_lif_input<<<(total + 255) / 256, 256>>>(x);
    }
    // K2: q/k GEMM + BN + LIF
    {
        dim3 grid(N_DIM / 64, (2 * C_DIM) / 64, B_DIM);
        k2_qk<<<grid, 256>>>(q_w, k_w, q_gamma, q_beta, q_mean, q_var,
                             k_gamma, k_beta, k_mean, k_var);
    }
    // K3: attention recurrence
    {
        int total = B_DIM * HEADS * N_DIM;
        k3_attn<<<(total + 255) / 256, 256>>>(alpha);
    }
    // K4: proj GEMM + bias + BN
    {
        dim3 grid(N_DIM / 64, C_DIM / 64, T_DIM * B_DIM);
        k4_proj<<<grid, 256>>>(proj_w, proj_b, proj_g, proj_be, proj_m, proj_v, out);
    }
}

// round 2
// speedup vs baseline: 2.1411x; 2.1411x over previous
#include <cuda_runtime.h>

#define T_DIM 4
#define B_DIM 64
#define C_DIM 256
#define N_DIM 256
#define HEADS 8
#define DHEAD 32
#define TAU 0.5f
#define THRESH 1.0f
#define ATTN_THRESH 0.5f
#define BN_EPS 1e-5f

#define OROWS 512   // stacked q(256)+k(256) output rows

// ---------------- scratch (static device globals) ----------------
__device__ float g_s[T_DIM * B_DIM * C_DIM * N_DIM];          // input spikes (T,B,C,N)
__device__ float g_u[T_DIM * B_DIM * OROWS * N_DIM];          // q/k pre-activations after BN
__device__ float g_qk[T_DIM * B_DIM * OROWS * N_DIM];         // q/k spikes
__device__ float g_attn[T_DIM * B_DIM * HEADS * N_DIM];       // attn spikes
__device__ float g_wt[C_DIM * OROWS];                         // transposed (c-major) [q_w;k_w]
__device__ float g_wpt[C_DIM * C_DIM];                        // transposed proj_w (c-major)
__device__ float g_inv[OROWS];                                // BN scale per stacked row
__device__ float g_add[OROWS];                                // BN shift per stacked row

// packed fp32x2 FMA (Blackwell f32x2 path; exact fp32 per lane)
__device__ __forceinline__ void ffma2(float2& d, const float2 a, const float2 b) {
    asm("fma.rn.f32x2 %0, %1, %2, %3;"
        : "=l"(*reinterpret_cast<unsigned long long*>(&d))
        : "l"(*reinterpret_cast<const unsigned long long*>(&a)),
          "l"(*reinterpret_cast<const unsigned long long*>(&b)),
          "l"(*reinterpret_cast<unsigned long long*>(&d)));
}

// ---------------- K0: weight transpose + BN constant prep ----------------
__global__ void k0_prep(const float* __restrict__ wq, const float* __restrict__ wk,
                        const float* __restrict__ wp,
                        const float* __restrict__ qg, const float* __restrict__ qb,
                        const float* __restrict__ qm, const float* __restrict__ qv,
                        const float* __restrict__ kg, const float* __restrict__ kb,
                        const float* __restrict__ km, const float* __restrict__ kv) {
    int c = blockIdx.x;          // 0..255
    int o = threadIdx.x;         // 0..511
    g_wt[c * OROWS + o] = (o < C_DIM) ? wq[o * C_DIM + c]
                                      : wk[(o - C_DIM) * C_DIM + c];
    if (o < C_DIM) g_wpt[c * C_DIM + o] = wp[o * C_DIM + c];
    if (c == 0) {
        float iv, ad;
        if (o < C_DIM) {
            iv = qg[o] * rsqrtf(qv[o] + BN_EPS);
            ad = qb[o] - qm[o] * iv;
        } else {
            int oo = o - C_DIM;
            iv = kg[oo] * rsqrtf(kv[oo] + BN_EPS);
            ad = kb[oo] - km[oo] * iv;
        }
        g_inv[o] = iv;
        g_add[o] = ad;
    }
}

// ---------------- K1: LIF over raw input -> s ----------------
__global__ void k1_lif_input(const float* __restrict__ x) {
    const int stride = B_DIM * C_DIM * N_DIM;
    int i = blockIdx.x * blockDim.x + threadIdx.x;
    if (i >= stride) return;
    float mem = 0.f;
#pragma unroll
    for (int t = 0; t < T_DIM; t++) {
        mem = mem * TAU + x[t * stride + i];
        float sp = (mem >= THRESH) ? 1.f : 0.f;
        mem *= (1.f - sp);
        g_s[t * stride + i] = sp;
    }
}

// ---------------- K2a: batched GEMM u = BN(W s), 128x128 tile, 8x8 micro ----------------
#define KK 16
__global__ __launch_bounds__(256, 2) void k2a_gemm_qk() {
    __shared__ float Wt[KK][128];
    __shared__ float St[KK][128];

    const int tb = blockIdx.z;                  // t*B + b
    const int ob = blockIdx.y * 128;            // over 512 stacked rows
    const int nb = blockIdx.x * 128;            // over N=256
    const int tid = threadIdx.x;
    const int tx = tid & 15, ty = tid >> 4;

    const float* sbase = g_s + (size_t)tb * C_DIM * N_DIM;

    float2 acc[8][4];
#pragma unroll
    for (int i = 0; i < 8; i++)
#pragma unroll
        for (int j = 0; j < 4; j++) acc[i][j] = make_float2(0.f, 0.f);

    for (int cc = 0; cc < C_DIM; cc += KK) {
        // Wt[kk][o_l] from g_wt[(cc+kk)*512 + ob + o_l]  (coalesced)
#pragma unroll
        for (int r = 0; r < 2; r++) {
            int idx = tid + r * 256;            // 512 float4 slots
            int row = idx >> 5, c4 = (idx & 31) << 2;
            *reinterpret_cast<float4*>(&Wt[row][c4]) =
                *reinterpret_cast<const float4*>(&g_wt[(cc + row) * OROWS + ob + c4]);
        }
        // St[kk][n_l] from s (coalesced)
#pragma unroll
        for (int r = 0; r < 2; r++) {
            int idx = tid + r * 256;
            int row = idx >> 5, c4 = (idx & 31) << 2;
            *reinterpret_cast<float4*>(&St[row][c4]) =
                *reinterpret_cast<const float4*>(&sbase[(cc + row) * N_DIM + nb + c4]);
        }
        __syncthreads();
#pragma unroll
        for (int kk = 0; kk < KK; kk++) {
            float4 a0 = *reinterpret_cast<const float4*>(&Wt[kk][ty * 8]);
            float4 a1 = *reinterpret_cast<const float4*>(&Wt[kk][ty * 8 + 4]);
            float4 b0 = *reinterpret_cast<const float4*>(&St[kk][tx * 8]);
            float4 b1 = *reinterpret_cast<const float4*>(&St[kk][tx * 8 + 4]);
            float2 bp[4] = {{b0.x, b0.y}, {b0.z, b0.w}, {b1.x, b1.y}, {b1.z, b1.w}};
            float ar[8] = {a0.x, a0.y, a0.z, a0.w, a1.x, a1.y, a1.z, a1.w};
#pragma unroll
            for (int i = 0; i < 8; i++) {
                float2 ap = make_float2(ar[i], ar[i]);
#pragma unroll
                for (int j = 0; j < 4; j++) ffma2(acc[i][j], ap, bp[j]);
            }
        }
        __syncthreads();
    }

    // epilogue: BN affine, store pre-activations
    float* ubase = g_u + (size_t)tb * OROWS * N_DIM;
#pragma unroll
    for (int i = 0; i < 8; i++) {
        int o = ob + ty * 8 + i;
        float iv = g_inv[o], ad = g_add[o];
        float4 v0, v1;
        v0.x = acc[i][0].x * iv + ad; v0.y = acc[i][0].y * iv + ad;
        v0.z = acc[i][1].x * iv + ad; v0.w = acc[i][1].y * iv + ad;
        v1.x = acc[i][2].x * iv + ad; v1.y = acc[i][2].y * iv + ad;
        v1.z = acc[i][3].x * iv + ad; v1.w = acc[i][3].y * iv + ad;
        *reinterpret_cast<float4*>(&ubase[o * N_DIM + nb + tx * 8]) = v0;
        *reinterpret_cast<float4*>(&ubase[o * N_DIM + nb + tx * 8 + 4]) = v1;
    }
}

// ---------------- K2b: LIF over t on u -> q/k spikes ----------------
__global__ void k2b_lif_qk() {
    const int stride = B_DIM * OROWS * N_DIM;
    int i = blockIdx.x * blockDim.x + threadIdx.x;
    if (i >= stride) return;
    float mem = 0.f;
#pragma unroll
    for (int t = 0; t < T_DIM; t++) {
        mem = mem * TAU + g_u[t * stride + i];
        float sp = (mem >= THRESH) ? 1.f : 0.f;
        mem *= (1.f - sp);
        g_qk[t * stride + i] = sp;
    }
}

// ---------------- K3: per-head channel sums + decay memory + attn LIF ----------------
__global__ void k3_attn(const float* __restrict__ alpha_p) {
    int i = blockIdx.x * blockDim.x + threadIdx.x;  // over B*HEADS*N
    if (i >= B_DIM * HEADS * N_DIM) return;
    int n = i % N_DIM;
    int h = (i / N_DIM) % HEADS;
    int b = i / (N_DIM * HEADS);
    float a = *alpha_p;
    float M = 0.f, amem = 0.f;
#pragma unroll
    for (int t = 0; t < T_DIM; t++) {
        const float* qbase =
            g_qk + ((size_t)(t * B_DIM + b) * OROWS + h * DHEAD) * N_DIM + n;
        float Q = 0.f;
#pragma unroll
        for (int d2 = 0; d2 < DHEAD; d2++) Q += qbase[d2 * N_DIM];
        M = (1.f - a) * M + a * Q;
        float qs = M + Q;
        amem = amem * TAU + qs;
        float sp = (amem >= ATTN_THRESH) ? 1.f : 0.f;
        amem *= (1.f - sp);
        g_attn[((t * B_DIM + b) * HEADS + h) * N_DIM + n] = sp;
    }
}

// ---------------- K4: proj GEMM over y = attn*k, 128x128 tile, 8x8 micro ----------------
__global__ __launch_bounds__(256, 2) void k4_proj(
    const float* __restrict__ pbias,
    const float* __restrict__ pg, const float* __restrict__ pbeta,
    const float* __restrict__ pm, const float* __restrict__ pv,
    float* __restrict__ out) {
    __shared__ float Wt[KK][128];
    __shared__ float St[KK][128];

    const int tb = blockIdx.z;
    const int ob = blockIdx.y * 128;
    const int nb = blockIdx.x * 128;
    const int tid = threadIdx.x;
    const int tx = tid & 15, ty = tid >> 4;

    const float* kbase = g_qk + ((size_t)tb * OROWS + C_DIM) * N_DIM;
    const float* abase = g_attn + (size_t)tb * HEADS * N_DIM;

    float2 acc[8][4];
#pragma unroll
    for (int i = 0; i < 8; i++)
#pragma unroll
        for (int j = 0; j < 4; j++) acc[i][j] = make_float2(0.f, 0.f);

    for (int cc = 0; cc < C_DIM; cc += KK) {
#pragma unroll
        for (int r = 0; r < 2; r++) {
            int idx = tid + r * 256;
            int row = idx >> 5, c4 = (idx & 31) << 2;
            *reinterpret_cast<float4*>(&Wt[row][c4]) =
                *reinterpret_cast<const float4*>(&g_wpt[(cc + row) * C_DIM + ob + c4]);
        }
#pragma unroll
        for (int r = 0; r < 2; r++) {
            int idx = tid + r * 256;
            int row = idx >> 5, c4 = (idx & 31) << 2;
            int c = cc + row;
            float4 kvv = *reinterpret_cast<const float4*>(&kbase[c * N_DIM + nb + c4]);
            float4 avv = *reinterpret_cast<const float4*>(&abase[(c >> 5) * N_DIM + nb + c4]);
            float4 yv;
            yv.x = kvv.x * avv.x; yv.y = kvv.y * avv.y;
            yv.z = kvv.z * avv.z; yv.w = kvv.w * avv.w;
            *reinterpret_cast<float4*>(&St[row][c4]) = yv;
        }
        __syncthreads();
#pragma unroll
        for (int kk = 0; kk < KK; kk++) {
            float4 a0 = *reinterpret_cast<const float4*>(&Wt[kk][ty * 8]);
            float4 a1 = *reinterpret_cast<const float4*>(&Wt[kk][ty * 8 + 4]);
            float4 b0 = *reinterpret_cast<const float4*>(&St[kk][tx * 8]);
            float4 b1 = *reinterpret_cast<const float4*>(&St[kk][tx * 8 + 4]);
            float2 bp[4] = {{b0.x, b0.y}, {b0.z, b0.w}, {b1.x, b1.y}, {b1.z, b1.w}};
            float ar[8] = {a0.x, a0.y, a0.z, a0.w, a1.x, a1.y, a1.z, a1.w};
#pragma unroll
            for (int i = 0; i < 8; i++) {
                float2 ap = make_float2(ar[i], ar[i]);
#pragma unroll
                for (int j = 0; j < 4; j++) ffma2(acc[i][j], ap, bp[j]);
            }
        }
        __syncthreads();
    }

#pragma unroll
    for (int i = 0; i < 8; i++) {
        int o = ob + ty * 8 + i;
        float iv = pg[o] * rsqrtf(pv[o] + BN_EPS);
        float ad = pbias[o] * iv + pbeta[o] - pm[o] * iv;
        float4 v0, v1;
        v0.x = acc[i][0].x * iv + ad; v0.y = acc[i][0].y * iv + ad;
        v0.z = acc[i][1].x * iv + ad; v0.w = acc[i][1].y * iv + ad;
        v1.x = acc[i][2].x * iv + ad; v1.y = acc[i][2].y * iv + ad;
        v1.z = acc[i][3].x * iv + ad; v1.w = acc[i][3].y * iv + ad;
        *reinterpret_cast<float4*>(&out[((size_t)tb * C_DIM + o) * N_DIM + nb + tx * 8]) = v0;
        *reinterpret_cast<float4*>(&out[((size_t)tb * C_DIM + o) * N_DIM + nb + tx * 8 + 4]) = v1;
    }
}

// ---------------- launch ----------------
extern "C" void kernel_launch(void* const* d_in, const int* in_sizes, int n_in,
                              void* d_out, int out_size) {
    const float* x       = (const float*)d_in[0];
    const float* q_w     = (const float*)d_in[1];
    const float* q_gamma = (const float*)d_in[2];
    const float* q_beta  = (const float*)d_in[3];
    const float* q_mean  = (const float*)d_in[4];
    const float* q_var   = (const float*)d_in[5];
    const float* k_w     = (const float*)d_in[6];
    const float* k_gamma = (const float*)d_in[7];
    const float* k_beta  = (const float*)d_in[8];
    const float* k_mean  = (const float*)d_in[9];
    const float* k_var   = (const float*)d_in[10];
    const float* proj_w  = (const float*)d_in[11];
    const float* proj_b  = (const float*)d_in[12];
    const float* proj_g  = (const float*)d_in[13];
    const float* proj_be = (const float*)d_in[14];
    const float* proj_m  = (const float*)d_in[15];
    const float* proj_v  = (const float*)d_in[16];
    const float* alpha   = (const float*)d_in[17];
    float* out = (float*)d_out;

    // K0: transpose weights, prep BN constants
    k0_prep<<<C_DIM, OROWS>>>(q_w, k_w, proj_w,
                              q_gamma, q_beta, q_mean, q_var,
                              k_gamma, k_beta, k_mean, k_var);
    // K1: input LIF
    {
        int total = B_DIM * C_DIM * N_DIM;
        k1_lif_input<<<(total + 255) / 256, 256>>>(x);
    }
    // K2a: q/k GEMM + BN (pre-activations)
    {
        dim3 grid(N_DIM / 128, OROWS / 128, T_DIM * B_DIM);
        k2a_gemm_qk<<<grid, 256>>>();
    }
    // K2b: LIF over t
    {
        int total = B_DIM * OROWS * N_DIM;
        k2b_lif_qk<<<(total + 255) / 256, 256>>>();
    }
    // K3: attention recurrence
    {
        int total = B_DIM * HEADS * N_DIM;
        k3_attn<<<(total + 255) / 256, 256>>>(alpha);
    }
    // K4: proj GEMM + bias + BN
    {
        dim3 grid(N_DIM / 128, C_DIM / 128, T_DIM * B_DIM);
        k4_proj<<<grid, 256>>>(proj_b, proj_g, proj_be, proj_m, proj_v, out);
    }
}

// round 4
// speedup vs baseline: 4.2695x; 1.9940x over previous
#include <cuda_runtime.h>
#include <cuda_fp16.h>
#include <cstdint>

#define T_DIM 4
#define B_DIM 64
#define C_DIM 256
#define N_DIM 256
#define HEADS 8
#define TAU 0.5f
#define THRESH 1.0f
#define ATTN_THRESH 0.5f
#define BN_EPS 1e-5f
#define OROWS 512
#define TB_TOT (T_DIM * B_DIM)
#define LO_SCALE 0.00048828125f   // 2^-11, exact power of two

#define SW128(b) ((b) ^ (((b) >> 3) & 0x70))

// ---------------- scratch ----------------
__device__ __align__(16) __half g_s[TB_TOT * N_DIM * 512];     // [tb][n][ s | s*2^-11 ]
__device__ __align__(16) float  g_u[TB_TOT * N_DIM * OROWS];   // preacts (tb,n,o)
__device__ __align__(16) __half g_qk[TB_TOT * N_DIM * OROWS];  // q/k spikes (tb,n,o)
__device__ __align__(16) __half g_attn[TB_TOT * N_DIM * HEADS];
__device__ __align__(16) __half g_w1[OROWS * 512];             // [o][ hi | lo*2^11 ]
__device__ __align__(16) __half g_w2[C_DIM * 512];
__device__ float g_inv[OROWS], g_add[OROWS];
__device__ float g_inv2[C_DIM], g_add2[C_DIM];

// ---------------- PTX helpers ----------------
__device__ __forceinline__ uint32_t smem_u32(const void* p) {
    uint32_t a;
    asm("{ .reg .u64 t; cvta.to.shared.u64 t, %1; cvt.u32.u64 %0, t; }" : "=r"(a) : "l"(p));
    return a;
}
__device__ __forceinline__ void ldmx4(uint32_t* r, uint32_t addr) {
    asm volatile("ldmatrix.sync.aligned.m8n8.x4.shared.b16 {%0,%1,%2,%3}, [%4];"
        : "=r"(r[0]), "=r"(r[1]), "=r"(r[2]), "=r"(r[3]) : "r"(addr));
}
__device__ __forceinline__ void mma16816(float* c, const uint32_t* a, uint32_t b0, uint32_t b1) {
    asm volatile("mma.sync.aligned.m16n8k16.row.col.f32.f16.f16.f32 "
        "{%0,%1,%2,%3}, {%4,%5,%6,%7}, {%8,%9}, {%0,%1,%2,%3};"
        : "+f"(c[0]), "+f"(c[1]), "+f"(c[2]), "+f"(c[3])
        : "r"(a[0]), "r"(a[1]), "r"(a[2]), "r"(a[3]), "r"(b0), "r"(b1));
}

// ---------------- K0: weight split + BN prep ----------------
__global__ void k0_prep(const float* __restrict__ wq, const float* __restrict__ wk,
                        const float* __restrict__ wp, const float* __restrict__ pb,
                        const float* __restrict__ qg, const float* __restrict__ qb,
                        const float* __restrict__ qm, const float* __restrict__ qv,
                        const float* __restrict__ kg, const float* __restrict__ kb,
                        const float* __restrict__ km, const float* __restrict__ kv,
                        const float* __restrict__ pg, const float* __restrict__ pbeta,
                        const float* __restrict__ pm, const float* __restrict__ pv) {
    int r = blockIdx.x;   // 0..767
    int c = threadIdx.x;  // 0..255
    if (r < OROWS) {
        float w = (r < C_DIM) ? wq[r * C_DIM + c] : wk[(r - C_DIM) * C_DIM + c];
        __half hi = __float2half_rn(w);
        float lo = (w - __half2float(hi)) * 2048.f;
        g_w1[r * 512 + c] = hi;
        g_w1[r * 512 + 256 + c] = __float2half_rn(lo);
        if (c == 0) {
            float iv, ad;
            if (r < C_DIM) { iv = qg[r] * rsqrtf(qv[r] + BN_EPS); ad = qb[r] - qm[r] * iv; }
            else { int o = r - C_DIM; iv = kg[o] * rsqrtf(kv[o] + BN_EPS); ad = kb[o] - km[o] * iv; }
            g_inv[r] = iv; g_add[r] = ad;
        }
    } else {
        int o = r - OROWS;
        float w = wp[o * C_DIM + c];
        __half hi = __float2half_rn(w);
        float lo = (w - __half2float(hi)) * 2048.f;
        g_w2[o * 512 + c] = hi;
        g_w2[o * 512 + 256 + c] = __float2half_rn(lo);
        if (c == 0) {
            float iv = pg[o] * rsqrtf(pv[o] + BN_EPS);
            g_inv2[o] = iv;
            g_add2[o] = pb[o] * iv + pbeta[o] - pm[o] * iv;
        }
    }
}

// ---------------- K1: input LIF + transpose -> g_s (tb,n,[s|s*2^-11]) ----------------
__global__ __launch_bounds__(1024) void k1_lif_input(const float* __restrict__ x) {
    __shared__ float tile[32][33];
    const int n0 = blockIdx.x * 32, c0 = blockIdx.y * 32, b = blockIdx.z;
    const int tid = threadIdx.x;
    const int cl = tid >> 5, nl = tid & 31;
    const int cl2 = tid & 31, nl2 = tid >> 5;
    float mem = 0.f;
#pragma unroll
    for (int t = 0; t < T_DIM; t++) {
        int tb = t * B_DIM + b;
        float v = x[((size_t)tb * C_DIM + c0 + cl) * N_DIM + n0 + nl];
        mem = mem * TAU + v;
        float sp = (mem >= THRESH) ? 1.f : 0.f;
        mem *= (1.f - sp);
        tile[cl][nl] = sp;
        __syncthreads();
        float s2 = tile[cl2][nl2];
        size_t base = ((size_t)tb * N_DIM + n0 + nl2) * 512 + c0 + cl2;
        g_s[base] = __float2half_rn(s2);
        g_s[base + 256] = __float2half_rn(s2 * LO_SCALE);
        __syncthreads();
    }
}

// ---------------- G1: mma.sync GEMM  u = BN(W1 @ s)  M=512 N=256 K=512 ----------------
// grid (4 mtiles, 2 ntiles, tb), 256 threads = 8 warps (4 m x 2 n), warp tile 32x64
__global__ __launch_bounds__(256) void g1_gemm() {
    __shared__ __align__(128) char sm[33 * 1024];
    __half* Ws = (__half*)sm;
    __half* Ss = (__half*)(sm + 16384);
    float* stage = (float*)sm;
    const uint32_t sb = smem_u32(sm);

    const int mtile = blockIdx.x, ntile = blockIdx.y, tb = blockIdx.z;
    const int tid = threadIdx.x, wid = tid >> 5, lane = tid & 31;
    const int warp_m = wid >> 1, warp_n = wid & 1;

    float acc[2][8][4];
#pragma unroll
    for (int i = 0; i < 2; i++)
#pragma unroll
        for (int j = 0; j < 8; j++)
#pragma unroll
            for (int q = 0; q < 4; q++) acc[i][j][q] = 0.f;

    const int a_row = warp_m * 32 + (lane & 7) + ((lane >> 3) & 1) * 8;
    const int a_kadd = (lane >> 4) * 8;
    const int b_row = warp_n * 64 + (lane & 7) + (lane >> 4) * 8;
    const int b_kadd = ((lane >> 3) & 1) * 8;

    const __half* Ag = g_w1 + (size_t)(mtile * 128) * 512;
    const __half* Bg = g_s + ((size_t)tb * N_DIM + ntile * 128) * 512;

    for (int ch = 0; ch < 8; ch++) {
        const int kc = ch * 64;
#pragma unroll
        for (int i = 0; i < 4; i++) {
            int idx = tid + i * 256;
            int row = idx >> 3, c16 = idx & 7;
            uint4 v = *reinterpret_cast<const uint4*>(Ag + row * 512 + kc + c16 * 8);
            *reinterpret_cast<uint4*>((char*)sm + SW128(row * 128 + c16 * 16)) = v;
        }
#pragma unroll
        for (int i = 0; i < 4; i++) {
            int idx = tid + i * 256;
            int row = idx >> 3, c16 = idx & 7;
            uint4 v = *reinterpret_cast<const uint4*>(Bg + row * 512 + kc + c16 * 8);
            *reinterpret_cast<uint4*>((char*)sm + 16384 + SW128(row * 128 + c16 * 16)) = v;
        }
        __syncthreads();
#pragma unroll
        for (int k16 = 0; k16 < 4; k16++) {
            uint32_t afr[2][4], bfr[4][4];
#pragma unroll
            for (int mb = 0; mb < 2; mb++)
                ldmx4(afr[mb], sb + SW128((a_row + mb * 16) * 128 + (k16 * 16 + a_kadd) * 2));
#pragma unroll
            for (int p = 0; p < 4; p++)
                ldmx4(bfr[p], sb + 16384 + SW128((b_row + p * 16) * 128 + (k16 * 16 + b_kadd) * 2));
#pragma unroll
            for (int mb = 0; mb < 2; mb++)
#pragma unroll
                for (int p = 0; p < 4; p++) {
                    mma16816(acc[mb][2 * p], afr[mb], bfr[p][0], bfr[p][1]);
                    mma16816(acc[mb][2 * p + 1], afr[mb], bfr[p][2], bfr[p][3]);
                }
        }
        __syncthreads();
    }

    // epilogue: BN + transpose via smem -> g_u (tb, n, o)
    for (int nc = 0; nc < 4; nc++) {
        if (warp_n == (nc >> 1)) {
            int nbb = (nc & 1) * 4;
#pragma unroll
            for (int mb = 0; mb < 2; mb++)
#pragma unroll
                for (int j = 0; j < 4; j++) {
                    int nb = nbb + j;
                    int o_l = warp_m * 32 + mb * 16 + (lane >> 2);
                    int nn = j * 8 + (lane & 3) * 2;
                    float iva = g_inv[mtile * 128 + o_l], ada = g_add[mtile * 128 + o_l];
                    float ivb = g_inv[mtile * 128 + o_l + 8], adb = g_add[mtile * 128 + o_l + 8];
                    stage[o_l * 33 + nn] = acc[mb][nb][0] * iva + ada;
                    stage[o_l * 33 + nn + 1] = acc[mb][nb][1] * iva + ada;
                    stage[(o_l + 8) * 33 + nn] = acc[mb][nb][2] * ivb + adb;
                    stage[(o_l + 8) * 33 + nn + 1] = acc[mb][nb][3] * ivb + adb;
                }
        }
        __syncthreads();
        {
            int n_l = tid >> 3, seg = tid & 7;
            float tmp[16];
#pragma unroll
            for (int j = 0; j < 16; j++) tmp[j] = stage[(seg * 16 + j) * 33 + n_l];
            float4* dst = reinterpret_cast<float4*>(
                g_u + ((size_t)tb * N_DIM + ntile * 128 + nc * 32 + n_l) * OROWS + mtile * 128 + seg * 16);
#pragma unroll
            for (int j = 0; j < 4; j++)
                dst[j] = make_float4(tmp[j * 4], tmp[j * 4 + 1], tmp[j * 4 + 2], tmp[j * 4 + 3]);
        }
        __syncthreads();
    }
}

// ---------------- K2b: LIF over t -> q/k spikes (fp16) ----------------
__global__ void k2b_lif_qk() {
    const int stride4 = B_DIM * N_DIM * OROWS / 4;
    int i = blockIdx.x * blockDim.x + threadIdx.x;
    if (i >= stride4) return;
    const float4* u4 = reinterpret_cast<const float4*>(g_u);
    float4 mem = make_float4(0.f, 0.f, 0.f, 0.f);
#pragma unroll
    for (int t = 0; t < T_DIM; t++) {
        float4 v = u4[t * stride4 + i];
        float4 sp;
        mem.x = mem.x * TAU + v.x; sp.x = (mem.x >= THRESH) ? 1.f : 0.f; mem.x *= (1.f - sp.x);
        mem.y = mem.y * TAU + v.y; sp.y = (mem.y >= THRESH) ? 1.f : 0.f; mem.y *= (1.f - sp.y);
        mem.z = mem.z * TAU + v.z; sp.z = (mem.z >= THRESH) ? 1.f : 0.f; mem.z *= (1.f - sp.z);
        mem.w = mem.w * TAU + v.w; sp.w = (mem.w >= THRESH) ? 1.f : 0.f; mem.w *= (1.f - sp.w);
        __half2 h0 = __floats2half2_rn(sp.x, sp.y);
        __half2 h1 = __floats2half2_rn(sp.z, sp.w);
        uint2* dst = reinterpret_cast<uint2*>(g_qk) + t * stride4 + i;
        *dst = make_uint2(*(uint32_t*)&h0, *(uint32_t*)&h1);
    }
}

// ---------------- K3: per-head sums + decay memory + attn LIF ----------------
__global__ void k3_attn(const float* __restrict__ alpha_p) {
    int i = blockIdx.x * blockDim.x + threadIdx.x;  // (b, n, h)
    if (i >= B_DIM * N_DIM * HEADS) return;
    int h = i & 7, n = (i >> 3) & 255, b = i >> 11;
    float a = *alpha_p;
    float M = 0.f, amem = 0.f;
#pragma unroll
    for (int t = 0; t < T_DIM; t++) {
        int tb = t * B_DIM + b;
        const __half2* qb2 = reinterpret_cast<const __half2*>(
            g_qk + ((size_t)tb * N_DIM + n) * OROWS + h * 32);
        float Q = 0.f;
#pragma unroll
        for (int j = 0; j < 16; j++) {
            float2 v = __half22float2(qb2[j]);
            Q += v.x + v.y;
        }
        M = (1.f - a) * M + a * Q;
        float qs = M + Q;
        amem = amem * TAU + qs;
        float sp = (amem >= ATTN_THRESH) ? 1.f : 0.f;
        amem *= (1.f - sp);
        g_attn[((size_t)tb * N_DIM + n) * HEADS + h] = __float2half_rn(sp);
    }
}

// ---------------- G2: mma.sync GEMM  out = BN(W2 @ (attn*k) + bias)  M=256 N=256 K=512 ----------------
__global__ __launch_bounds__(256) void g2_gemm(float* __restrict__ out) {
    __shared__ __align__(128) char sm[32 * 1024];
    const uint32_t sb = smem_u32(sm);

    const int mtile = blockIdx.x, ntile = blockIdx.y, tb = blockIdx.z;
    const int tid = threadIdx.x, wid = tid >> 5, lane = tid & 31;
    const int warp_m = wid >> 1, warp_n = wid & 1;

    float acc[2][8][4];
#pragma unroll
    for (int i = 0; i < 2; i++)
#pragma unroll
        for (int j = 0; j < 8; j++)
#pragma unroll
            for (int q = 0; q < 4; q++) acc[i][j][q] = 0.f;

    const int a_row = warp_m * 32 + (lane & 7) + ((lane >> 3) & 1) * 8;
    const int a_kadd = (lane >> 4) * 8;
    const int b_row = warp_n * 64 + (lane & 7) + (lane >> 4) * 8;
    const int b_kadd = ((lane >> 3) & 1) * 8;

    const __half* Ag = g_w2 + (size_t)(mtile * 128) * 512;
    const __half* Kg = g_qk + ((size_t)tb * N_DIM + ntile * 128) * OROWS;
    const __half* Atn = g_attn + ((size_t)tb * N_DIM + ntile * 128) * HEADS;

    for (int ch = 0; ch < 8; ch++) {
        const int kc = ch * 64;
#pragma unroll
        for (int i = 0; i < 4; i++) {
            int idx = tid + i * 256;
            int row = idx >> 3, c16 = idx & 7;
            uint4 v = *reinterpret_cast<const uint4*>(Ag + row * 512 + kc + c16 * 8);
            *reinterpret_cast<uint4*>((char*)sm + SW128(row * 128 + c16 * 16)) = v;
        }
#pragma unroll
        for (int i = 0; i < 4; i++) {
            int idx = tid + i * 256;
            int row = idx >> 3, c16 = idx & 7;
            int k = kc + c16 * 8;
            int c8 = k & 255;
            uint4 v = *reinterpret_cast<const uint4*>(Kg + row * OROWS + 256 + c8);
            float af = __half2float(Atn[row * HEADS + (c8 >> 5)]);
            float scf = (k < 256) ? af : af * LO_SCALE;
            __half2 s2 = __floats2half2_rn(scf, scf);
            __half2* hv = reinterpret_cast<__half2*>(&v);
#pragma unroll
            for (int q = 0; q < 4; q++) hv[q] = __hmul2(hv[q], s2);
            *reinterpret_cast<uint4*>((char*)sm + 16384 + SW128(row * 128 + c16 * 16)) = v;
        }
        __syncthreads();
#pragma unroll
        for (int k16 = 0; k16 < 4; k16++) {
            uint32_t afr[2][4], bfr[4][4];
#pragma unroll
            for (int mb = 0; mb < 2; mb++)
                ldmx4(afr[mb], sb + SW128((a_row + mb * 16) * 128 + (k16 * 16 + a_kadd) * 2));
#pragma unroll
            for (int p = 0; p < 4; p++)
                ldmx4(bfr[p], sb + 16384 + SW128((b_row + p * 16) * 128 + (k16 * 16 + b_kadd) * 2));
#pragma unroll
            for (int mb = 0; mb < 2; mb++)
#pragma unroll
                for (int p = 0; p < 4; p++) {
                    mma16816(acc[mb][2 * p], afr[mb], bfr[p][0], bfr[p][1]);
                    mma16816(acc[mb][2 * p + 1], afr[mb], bfr[p][2], bfr[p][3]);
                }
        }
        __syncthreads();
    }

    // epilogue: BN + bias, direct store to out (tb, o, n)
#pragma unroll
    for (int mb = 0; mb < 2; mb++) {
        int o0 = mtile * 128 + warp_m * 32 + mb * 16 + (lane >> 2);
        float iva = g_inv2[o0], ada = g_add2[o0];
        float ivb = g_inv2[o0 + 8], adb = g_add2[o0 + 8];
#pragma unroll
        for (int nb = 0; nb < 8; nb++) {
            int n_g = ntile * 128 + warp_n * 64 + nb * 8 + (lane & 3) * 2;
            float2 v0 = make_float2(acc[mb][nb][0] * iva + ada, acc[mb][nb][1] * iva + ada);
            float2 v1 = make_float2(acc[mb][nb][2] * ivb + adb, acc[mb][nb][3] * ivb + adb);
            *reinterpret_cast<float2*>(out + ((size_t)tb * C_DIM + o0) * N_DIM + n_g) = v0;
            *reinterpret_cast<float2*>(out + ((size_t)tb * C_DIM + o0 + 8) * N_DIM + n_g) = v1;
        }
    }
}

// ---------------- launch ----------------
extern "C" void kernel_launch(void* const* d_in, const int* in_sizes, int n_in,
                              void* d_out, int out_size) {
    const float* x       = (const float*)d_in[0];
    const float* q_w     = (const float*)d_in[1];
    const float* q_gamma = (const float*)d_in[2];
    const float* q_beta  = (const float*)d_in[3];
    const float* q_mean  = (const float*)d_in[4];
    const float* q_var   = (const float*)d_in[5];
    const float* k_w     = (const float*)d_in[6];
    const float* k_gamma = (const float*)d_in[7];
    const float* k_beta  = (const float*)d_in[8];
    const float* k_mean  = (const float*)d_in[9];
    const float* k_var   = (const float*)d_in[10];
    const float* proj_w  = (const float*)d_in[11];
    const float* proj_b  = (const float*)d_in[12];
    const float* proj_g  = (const float*)d_in[13];
    const float* proj_be = (const float*)d_in[14];
    const float* proj_m  = (const float*)d_in[15];
    const float* proj_v  = (const float*)d_in[16];
    const float* alpha   = (const float*)d_in[17];
    float* out = (float*)d_out;

    k0_prep<<<OROWS + C_DIM, 256>>>(q_w, k_w, proj_w, proj_b,
                                    q_gamma, q_beta, q_mean, q_var,
                                    k_gamma, k_beta, k_mean, k_var,
                                    proj_g, proj_be, proj_m, proj_v);
    {
        dim3 grid(N_DIM / 32, C_DIM / 32, B_DIM);
        k1_lif_input<<<grid, 1024>>>(x);
    }
    {
        dim3 grid(4, 2, TB_TOT);
        g1_gemm<<<grid, 256>>>();
    }
    {
        int total4 = B_DIM * N_DIM * OROWS / 4;
        k2b_lif_qk<<<(total4 + 255) / 256, 256>>>();
    }
    {
        int total = B_DIM * N_DIM * HEADS;
        k3_attn<<<(total + 255) / 256, 256>>>(alpha);
    }
    {
        dim3 grid(2, 2, TB_TOT);
        g2_gemm<<<grid, 256>>>(out);
    }
}